// round 13
// baseline (speedup 1.0000x reference)
#include <cuda_runtime.h>
#include <cuda_fp16.h>
#include <cstdint>

#define Bx    2
#define Lx    2048
#define Dx    1024
#define Hx    16
#define DHx   64
#define CKx   64
#define NCH   32          // Lx / CKx
#define ROWSx 4096        // Bx * Lx
#define BHx   32          // Bx * Hx

// Scratch (device globals: no allocation allowed in kernel_launch)
__device__ __align__(16) __half g_qkvh[ROWSx * 3 * Dx];  // fp16 qkv (GEMM1 out)
__device__ float  g_M[BHx * NCH * DHx * DHx];            // per-chunk states (fp32)
__device__ __align__(16) __half g_Ph[BHx * NCH * DHx * DHx]; // exclusive prefix (fp16)
__device__ __align__(16) __half g_xh[ROWSx * Dx];        // fp16 x
__device__ __align__(16) __half g_wqh[3 * Dx * Dx];      // fp16 Wqkv_w
__device__ __align__(16) __half g_woh[Dx * Dx];          // fp16 out_w
__device__ __align__(16) __half g_yh[ROWSx * Dx];        // fp16 y (intra, then final)

// ============================================================================
// helpers (all non-"a" instructions: safe on plain sm_103 target)
// ============================================================================
__device__ __forceinline__ uint32_t smem_u32(const void* p) {
    uint32_t a;
    asm("{ .reg .u64 t; cvta.to.shared.u64 t, %1; cvt.u32.u64 %0, t; }"
        : "=r"(a) : "l"(p));
    return a;
}

#define CP16(dst, src) \
    asm volatile("cp.async.cg.shared.global [%0], [%1], 16;" :: "r"(dst), "l"(src) : "memory")
#define CP_COMMIT() asm volatile("cp.async.commit_group;" ::: "memory")
#define CP_WAIT0()  asm volatile("cp.async.wait_group 0;" ::: "memory")
#define CP_WAIT1()  asm volatile("cp.async.wait_group 1;" ::: "memory")

#define LDSM4(r0, r1, r2, r3, addr) \
    asm volatile("ldmatrix.sync.aligned.m8n8.x4.shared.b16 {%0,%1,%2,%3}, [%4];" \
                 : "=r"(r0), "=r"(r1), "=r"(r2), "=r"(r3) : "r"(addr))

#define LDSM4T(r0, r1, r2, r3, addr) \
    asm volatile("ldmatrix.sync.aligned.m8n8.x4.trans.shared.b16 {%0,%1,%2,%3}, [%4];" \
                 : "=r"(r0), "=r"(r1), "=r"(r2), "=r"(r3) : "r"(addr))

#define MMA_F16(d, a, b) \
    asm volatile("mma.sync.aligned.m16n8k16.row.col.f32.f16.f16.f32 " \
                 "{%0,%1,%2,%3}, {%4,%5,%6,%7}, {%8,%9}, {%0,%1,%2,%3};" \
                 : "+f"((d)[0]), "+f"((d)[1]), "+f"((d)[2]), "+f"((d)[3]) \
                 : "r"((a)[0]), "r"((a)[1]), "r"((a)[2]), "r"((a)[3]), \
                   "r"((b)[0]), "r"((b)[1]))

__device__ __forceinline__ void st2(float* p, float x, float y) {
    *(float2*)p = make_float2(x, y);
}
__device__ __forceinline__ void st2(__half* p, float x, float y) {
    *(__half2*)p = __floats2half2_rn(x, y);
}

// ============================================================================
// fused fp32 -> fp16 conversion of x, Wqkv_w, out_w (one launch)
// ============================================================================
#define NX4 (ROWSx * Dx / 4)        // 1048576
#define NQ4 (3 * Dx * Dx / 4)       // 786432
#define NO4 (Dx * Dx / 4)           // 262144

__global__ void __launch_bounds__(256) f2h_all_kernel(
    const float* __restrict__ x, const float* __restrict__ wq,
    const float* __restrict__ wo)
{
    int i = blockIdx.x * 256 + threadIdx.x;
    const float* src;
    __half* dst;
    int j;
    if (i < NX4) { src = x; dst = g_xh; j = i; }
    else if (i < NX4 + NQ4) { src = wq; dst = g_wqh; j = i - NX4; }
    else if (i < NX4 + NQ4 + NO4) { src = wo; dst = g_woh; j = i - NX4 - NQ4; }
    else return;
    float4 v = ((const float4*)src)[j];
    ((__half2*)dst)[2 * j + 0] = __floats2half2_rn(v.x, v.y);
    ((__half2*)dst)[2 * j + 1] = __floats2half2_rn(v.z, v.w);
}

// ============================================================================
// fp16 tensor-core GEMM (NT), PERSISTENT: C[M,N] = A[M,K] @ W[N,K]^T + bias[N]
// CTA 128x128, BK=64 halves, 256 thr (8 warps 4x2, warp tile 32x64),
// 3-stage cp.async, 96KB smem, 2 CTAs/SM. Grid = 2*SMs; each CTA loops over
// tiles (removes the 0.4-wave quantization tail of the 768-tile launch).
// ============================================================================
#define TBM 128
#define TBN 128
#define HBK 64
#define TSTG_BYTES (TBM * 128 + TBN * 128)           // 32768
#define TSMEM_TOTAL (3 * TSTG_BYTES)                 // 98304
#define GEMM_GRID 296                                // 148 SMs * 2 CTAs

__device__ __forceinline__ void tload(uint32_t stg, const __half* __restrict__ A,
                                      const __half* __restrict__ W, int K,
                                      int bm, int bn, int k0, int tid)
{
    #pragma unroll
    for (int j = 0; j < 4; j++) {
        int e = tid + j * 256;
        int r = e >> 3, c16 = e & 7;
        uint32_t dst = stg + (uint32_t)(r * 128 + ((c16 ^ (r & 7)) << 4));
        CP16(dst, A + (size_t)(bm + r) * K + k0 + c16 * 8);
    }
    #pragma unroll
    for (int j = 0; j < 4; j++) {
        int e = tid + j * 256;
        int r = e >> 3, c16 = e & 7;
        uint32_t dst = stg + 16384u + (uint32_t)(r * 128 + ((c16 ^ (r & 7)) << 4));
        CP16(dst, W + (size_t)(bn + r) * K + k0 + c16 * 8);
    }
}

template <typename OT>
__global__ void __launch_bounds__(256, 2) gemm_tc_bias(
    const __half* __restrict__ A, const __half* __restrict__ W,
    const float* __restrict__ bias, OT* __restrict__ C,
    int M, int N, int K, int ntiles_n, int ntiles)
{
    extern __shared__ char smem[];
    const uint32_t sb = smem_u32(smem);
    const int tid = threadIdx.x;
    const int lane = tid & 31, wid = tid >> 5;
    const int wm = wid & 3, wn = wid >> 2;
    const int NK = K / HBK;

    const int lrow = lane & 15;
    const int lkc  = lane >> 4;
    const int l7   = lrow & 7;

    uint32_t aRow[2], bRow[4];
    #pragma unroll
    for (int mt = 0; mt < 2; mt++) aRow[mt] = (uint32_t)((wm * 32 + mt * 16 + lrow) * 128);
    #pragma unroll
    for (int p = 0; p < 4; p++)    bRow[p] = (uint32_t)((wn * 64 + p * 16 + lrow) * 128);

    const int erow = lane >> 2;
    const int ecol = (lane & 3) * 2;

    for (int t = blockIdx.x; t < ntiles; t += gridDim.x) {
        const int bm = (t / ntiles_n) * TBM;
        const int bn = (t % ntiles_n) * TBN;

        // fence previous tile's smem reads vs new prologue writes
        __syncthreads();

        float d[2][8][4];
        #pragma unroll
        for (int mt = 0; mt < 2; mt++)
            #pragma unroll
            for (int nt = 0; nt < 8; nt++)
                #pragma unroll
                for (int i = 0; i < 4; i++) d[mt][nt][i] = 0.f;

        tload(sb, A, W, K, bm, bn, 0, tid);
        CP_COMMIT();
        tload(sb + TSTG_BYTES, A, W, K, bm, bn, HBK, tid);
        CP_COMMIT();

        int s0 = 0, s2 = 2;
        for (int i = 0; i < NK; i++) {
            CP_WAIT1();
            __syncthreads();
            if (i + 2 < NK)
                tload(sb + (uint32_t)(s2 * TSTG_BYTES), A, W, K, bm, bn, (i + 2) * HBK, tid);
            CP_COMMIT();

            const uint32_t sA = sb + (uint32_t)(s0 * TSTG_BYTES);
            const uint32_t sB = sA + 16384u;

            #pragma unroll
            for (int ks = 0; ks < 4; ks++) {
                const int kc = ks * 2;
                const uint32_t swz = (uint32_t)(((kc + lkc) ^ l7) << 4);

                uint32_t a[2][4];
                #pragma unroll
                for (int mt = 0; mt < 2; mt++)
                    LDSM4(a[mt][0], a[mt][1], a[mt][2], a[mt][3], sA + aRow[mt] + swz);

                uint32_t b[8][2];
                #pragma unroll
                for (int p = 0; p < 4; p++) {
                    uint32_t r0, r1, r2, r3;
                    LDSM4(r0, r1, r2, r3, sB + bRow[p] + swz);
                    b[2 * p][0] = r0; b[2 * p + 1][0] = r1;
                    b[2 * p][1] = r2; b[2 * p + 1][1] = r3;
                }

                #pragma unroll
                for (int mt = 0; mt < 2; mt++)
                    #pragma unroll
                    for (int nt = 0; nt < 8; nt++)
                        MMA_F16(d[mt][nt], a[mt], b[nt]);
            }
            s0 = (s0 == 2) ? 0 : s0 + 1;
            s2 = (s2 == 2) ? 0 : s2 + 1;
        }

        #pragma unroll
        for (int mt = 0; mt < 2; mt++) {
            const int r0 = bm + wm * 32 + mt * 16 + erow;
            #pragma unroll
            for (int nt = 0; nt < 8; nt++) {
                const int c = bn + wn * 64 + nt * 8 + ecol;
                float2 bv = *(const float2*)(bias + c);
                st2(C + (size_t)r0 * N + c, d[mt][nt][0] + bv.x, d[mt][nt][1] + bv.y);
                st2(C + (size_t)(r0 + 8) * N + c, d[mt][nt][2] + bv.x, d[mt][nt][3] + bv.y);
            }
        }
    }
}

// ============================================================================
// Attention kernel A (fp16 MMA): per (bh, chunk) of 64 tokens:
//   S = tril(Q K^T) * 0.125 ;  Y_intra -> g_yh (fp16) ;  M = V^T K * 0.125 -> g_M
// 128 threads (4 warps), warp tile 16x64.
// ============================================================================
__global__ void __launch_bounds__(128) attn_intra_kernel()
{
    __shared__ __half sQ[64 * 64], sK[64 * 64], sV[64 * 64], sS[64 * 64];

    const int tid = threadIdx.x, lane = tid & 31, w = tid >> 5;
    const int chunk = blockIdx.x, bh = blockIdx.y;
    const int b = bh >> 4, h = bh & 15;

    const uint32_t q_s = smem_u32(sQ), k_s = smem_u32(sK);
    const uint32_t v_s = smem_u32(sV), s_s = smem_u32(sS);

    const __half* base = g_qkvh + (size_t)(b * Lx + chunk * CKx) * (3 * Dx) + h * DHx;
    #pragma unroll
    for (int j = 0; j < 4; j++) {
        int e = tid + j * 128;
        int r = e >> 3, c16 = e & 7;
        uint32_t off = (uint32_t)(r * 128 + ((c16 ^ (r & 7)) << 4));
        const __half* src = base + (size_t)r * (3 * Dx) + c16 * 8;
        CP16(q_s + off, src);
        CP16(k_s + off, src + Dx);
        CP16(v_s + off, src + 2 * Dx);
    }
    CP_COMMIT();
    CP_WAIT0();
    __syncthreads();

    const int lrow = lane & 15, lkc = lane >> 4, l7 = lrow & 7;
    const int erow = lane >> 2, ecol = (lane & 3) * 2;
    const uint32_t aRowOff = (uint32_t)((w * 16 + lrow) * 128);

    // ---- Phase 1: S = Q K^T (NT) ----
    float accS[8][4];
    #pragma unroll
    for (int nt = 0; nt < 8; nt++)
        #pragma unroll
        for (int i = 0; i < 4; i++) accS[nt][i] = 0.f;

    #pragma unroll
    for (int ks = 0; ks < 4; ks++) {
        const uint32_t swz = (uint32_t)(((ks * 2 + lkc) ^ l7) << 4);
        uint32_t a[4];
        LDSM4(a[0], a[1], a[2], a[3], q_s + aRowOff + swz);
        uint32_t bfr[8][2];
        #pragma unroll
        for (int p = 0; p < 4; p++) {
            uint32_t r0, r1, r2, r3;
            LDSM4(r0, r1, r2, r3, k_s + (uint32_t)((p * 16 + lrow) * 128) + swz);
            bfr[2 * p][0] = r0; bfr[2 * p + 1][0] = r1;
            bfr[2 * p][1] = r2; bfr[2 * p + 1][1] = r3;
        }
        #pragma unroll
        for (int nt = 0; nt < 8; nt++) MMA_F16(accS[nt], a, bfr[nt]);
    }

    // scale + causal mask + fp16 -> sS (swizzled)
    #pragma unroll
    for (int nt = 0; nt < 8; nt++) {
        const int i0 = w * 16 + erow, i1 = i0 + 8;
        const int j0 = nt * 8 + ecol;
        float s00 = (i0 >= j0)     ? accS[nt][0] * 0.125f : 0.f;
        float s01 = (i0 >= j0 + 1) ? accS[nt][1] * 0.125f : 0.f;
        float s10 = (i1 >= j0)     ? accS[nt][2] * 0.125f : 0.f;
        float s11 = (i1 >= j0 + 1) ? accS[nt][3] * 0.125f : 0.f;
        const uint32_t cb = (uint32_t)(j0 * 2);
        uint32_t o0 = (uint32_t)(i0 * 128) + (((cb >> 4) ^ (uint32_t)(i0 & 7)) << 4) + (cb & 15);
        uint32_t o1 = (uint32_t)(i1 * 128) + (((cb >> 4) ^ (uint32_t)(i1 & 7)) << 4) + (cb & 15);
        *(__half2*)((char*)sS + o0) = __floats2half2_rn(s00, s01);
        *(__half2*)((char*)sS + o1) = __floats2half2_rn(s10, s11);
    }
    __syncthreads();

    // ---- Phase 2: Y = S V (NN: B via ldmatrix.trans) -> fp16 g_yh ----
    float accY[8][4];
    #pragma unroll
    for (int nt = 0; nt < 8; nt++)
        #pragma unroll
        for (int i = 0; i < 4; i++) accY[nt][i] = 0.f;

    #pragma unroll
    for (int ks = 0; ks < 4; ks++) {
        const int kbase = ks * 16;
        const uint32_t swz = (uint32_t)(((ks * 2 + lkc) ^ l7) << 4);
        uint32_t a[4];
        LDSM4(a[0], a[1], a[2], a[3], s_s + aRowOff + swz);
        uint32_t bfr[8][2];
        #pragma unroll
        for (int nb = 0; nb < 4; nb++) {
            const int vr = kbase + lrow;
            const uint32_t c16 = (uint32_t)(nb * 2 + lkc);
            uint32_t r0, r1, r2, r3;
            LDSM4T(r0, r1, r2, r3, v_s + (uint32_t)(vr * 128) + ((c16 ^ (uint32_t)(vr & 7)) << 4));
            bfr[2 * nb][0] = r0; bfr[2 * nb][1] = r1;
            bfr[2 * nb + 1][0] = r2; bfr[2 * nb + 1][1] = r3;
        }
        #pragma unroll
        for (int nt = 0; nt < 8; nt++) MMA_F16(accY[nt], a, bfr[nt]);
    }

    __half* yb = g_yh + (size_t)(b * Lx + chunk * CKx) * Dx + h * DHx;
    #pragma unroll
    for (int nt = 0; nt < 8; nt++) {
        const int i0 = w * 16 + erow, j0 = nt * 8 + ecol;
        st2(yb + (size_t)i0 * Dx + j0, accY[nt][0], accY[nt][1]);
        st2(yb + (size_t)(i0 + 8) * Dx + j0, accY[nt][2], accY[nt][3]);
    }

    // ---- Phase 3: M = V^T K * 0.125 (A via trans, B via trans) ----
    float accM[8][4];
    #pragma unroll
    for (int nt = 0; nt < 8; nt++)
        #pragma unroll
        for (int i = 0; i < 4; i++) accM[nt][i] = 0.f;

    const int arow_lo = (lane & 7) + ((lane >> 4) << 3);
    const uint32_t ac16 = (uint32_t)(((w * 16) >> 3) + ((lane >> 3) & 1));

    #pragma unroll
    for (int ks = 0; ks < 4; ks++) {
        const int kbase = ks * 16;
        const int vr = kbase + arow_lo;
        uint32_t a[4];
        LDSM4T(a[0], a[1], a[2], a[3],
               v_s + (uint32_t)(vr * 128) + ((ac16 ^ (uint32_t)(vr & 7)) << 4));
        uint32_t bfr[8][2];
        #pragma unroll
        for (int nb = 0; nb < 4; nb++) {
            const int kr = kbase + lrow;
            const uint32_t c16 = (uint32_t)(nb * 2 + lkc);
            uint32_t r0, r1, r2, r3;
            LDSM4T(r0, r1, r2, r3, k_s + (uint32_t)(kr * 128) + ((c16 ^ (uint32_t)(kr & 7)) << 4));
            bfr[2 * nb][0] = r0; bfr[2 * nb][1] = r1;
            bfr[2 * nb + 1][0] = r2; bfr[2 * nb + 1][1] = r3;
        }
        #pragma unroll
        for (int nt = 0; nt < 8; nt++) MMA_F16(accM[nt], a, bfr[nt]);
    }

    float* Mb = g_M + (size_t)(bh * NCH + chunk) * (DHx * DHx);
    #pragma unroll
    for (int nt = 0; nt < 8; nt++) {
        const int a0 = w * 16 + erow, j0 = nt * 8 + ecol;
        st2(Mb + a0 * 64 + j0, accM[nt][0] * 0.125f, accM[nt][1] * 0.125f);
        st2(Mb + (a0 + 8) * 64 + j0, accM[nt][2] * 0.125f, accM[nt][3] * 0.125f);
    }
}

// ---------------------------------------------------------------------------
// Exclusive prefix over chunks: load all 32 M-values first (independent LDGs,
// MLP=32) then prefix in registers and store.
// ---------------------------------------------------------------------------
__global__ void __launch_bounds__(256) prefix_kernel()
{
    const int bh = blockIdx.y;
    const int e = blockIdx.x * 256 + threadIdx.x;   // 0..4095
    size_t base = (size_t)bh * NCH * (DHx * DHx) + e;

    float m[NCH];
    #pragma unroll
    for (int c = 0; c < NCH; c++)
        m[c] = g_M[base + (size_t)c * (DHx * DHx)];

    float acc = 0.f;
    #pragma unroll
    for (int c = 0; c < NCH; c++) {
        g_Ph[base + (size_t)c * (DHx * DHx)] = __float2half_rn(acc);
        acc += m[c];
    }
}

// ============================================================================
// Attention kernel C (fp16 MMA): y_final = y_intra(fp16, in g_yh) + Q P^T,
// in-place RMW on g_yh.  128 threads (4 warps), warp tile 16x64.
// ============================================================================
__global__ void __launch_bounds__(128) attn_inter_kernel()
{
    __shared__ __half sQ[64 * 64], sP[64 * 64];

    const int tid = threadIdx.x, lane = tid & 31, w = tid >> 5;
    const int chunk = blockIdx.x, bh = blockIdx.y;
    const int b = bh >> 4, h = bh & 15;

    const uint32_t q_s = smem_u32(sQ), p_s = smem_u32(sP);

    const __half* qbase = g_qkvh + (size_t)(b * Lx + chunk * CKx) * (3 * Dx) + h * DHx;
    const __half* Pbase = g_Ph + (size_t)(bh * NCH + chunk) * (DHx * DHx);
    #pragma unroll
    for (int j = 0; j < 4; j++) {
        int e = tid + j * 128;
        int r = e >> 3, c16 = e & 7;
        uint32_t off = (uint32_t)(r * 128 + ((c16 ^ (r & 7)) << 4));
        CP16(q_s + off, qbase + (size_t)r * (3 * Dx) + c16 * 8);
        CP16(p_s + off, Pbase + r * 64 + c16 * 8);
    }
    CP_COMMIT();
    CP_WAIT0();
    __syncthreads();

    const int lrow = lane & 15, lkc = lane >> 4, l7 = lrow & 7;
    const int erow = lane >> 2, ecol = (lane & 3) * 2;
    const uint32_t aRowOff = (uint32_t)((w * 16 + lrow) * 128);

    float acc[8][4];
    #pragma unroll
    for (int nt = 0; nt < 8; nt++)
        #pragma unroll
        for (int i = 0; i < 4; i++) acc[nt][i] = 0.f;

    #pragma unroll
    for (int ks = 0; ks < 4; ks++) {
        const uint32_t swz = (uint32_t)(((ks * 2 + lkc) ^ l7) << 4);
        uint32_t a[4];
        LDSM4(a[0], a[1], a[2], a[3], q_s + aRowOff + swz);
        uint32_t bfr[8][2];
        #pragma unroll
        for (int p = 0; p < 4; p++) {
            uint32_t r0, r1, r2, r3;
            LDSM4(r0, r1, r2, r3, p_s + (uint32_t)((p * 16 + lrow) * 128) + swz);
            bfr[2 * p][0] = r0; bfr[2 * p + 1][0] = r1;
            bfr[2 * p][1] = r2; bfr[2 * p + 1][1] = r3;
        }
        #pragma unroll
        for (int nt = 0; nt < 8; nt++) MMA_F16(acc[nt], a, bfr[nt]);
    }

    __half* yh = g_yh + (size_t)(b * Lx + chunk * CKx) * Dx + h * DHx;
    #pragma unroll
    for (int nt = 0; nt < 8; nt++) {
        const int i0 = w * 16 + erow, j0 = nt * 8 + ecol;
        float2 v0 = __half22float2(*(__half2*)(yh + (size_t)i0 * Dx + j0));
        float2 v1 = __half22float2(*(__half2*)(yh + (size_t)(i0 + 8) * Dx + j0));
        *(__half2*)(yh + (size_t)i0 * Dx + j0) =
            __floats2half2_rn(v0.x + acc[nt][0], v0.y + acc[nt][1]);
        *(__half2*)(yh + (size_t)(i0 + 8) * Dx + j0) =
            __floats2half2_rn(v1.x + acc[nt][2], v1.y + acc[nt][3]);
    }
}

// ---------------------------------------------------------------------------
extern "C" void kernel_launch(void* const* d_in, const int* in_sizes, int n_in,
                              void* d_out, int out_size)
{
    const float* x      = (const float*)d_in[0];   // [2,2048,1024]
    const float* Wqkv_w = (const float*)d_in[1];   // [3072,1024]
    const float* Wqkv_b = (const float*)d_in[2];   // [3072]
    const float* out_w  = (const float*)d_in[3];   // [1024,1024]
    const float* out_b  = (const float*)d_in[4];   // [1024]
    float* out = (float*)d_out;                    // [2,2048,1024]

    __half *qkvh_ptr, *xh_ptr, *wq_ptr, *wo_ptr, *yh_ptr;
    cudaGetSymbolAddress((void**)&qkvh_ptr, g_qkvh);
    cudaGetSymbolAddress((void**)&xh_ptr, g_xh);
    cudaGetSymbolAddress((void**)&wq_ptr, g_wqh);
    cudaGetSymbolAddress((void**)&wo_ptr, g_woh);
    cudaGetSymbolAddress((void**)&yh_ptr, g_yh);

    cudaFuncSetAttribute(gemm_tc_bias<__half>,
                         cudaFuncAttributeMaxDynamicSharedMemorySize, TSMEM_TOTAL);
    cudaFuncSetAttribute(gemm_tc_bias<float>,
                         cudaFuncAttributeMaxDynamicSharedMemorySize, TSMEM_TOTAL);

    // 0. fused fp16 conversion of GEMM operands (one launch)
    f2h_all_kernel<<<(NX4 + NQ4 + NO4 + 255) / 256, 256>>>(x, Wqkv_w, out_w);

    // 1. QKV projection -> fp16 qkv  (persistent: 296 CTAs over 768 tiles)
    {
        int tiles_n = 3072 / TBN, tiles = (ROWSx / TBM) * tiles_n;  // 24, 768
        int grid = tiles < GEMM_GRID ? tiles : GEMM_GRID;
        gemm_tc_bias<__half><<<grid, 256, TSMEM_TOTAL>>>(
            xh_ptr, wq_ptr, Wqkv_b, qkvh_ptr, ROWSx, 3 * Dx, Dx, tiles_n, tiles);
    }

    // 2a. Intra-chunk attention + per-chunk states -> g_yh (fp16), g_M
    attn_intra_kernel<<<dim3(NCH, BHx), 128>>>();

    // 2b. Exclusive prefix of states (MLP-32 loads, fp32 acc -> fp16 P)
    prefix_kernel<<<dim3(16, BHx), 256>>>();

    // 2c. Inter-chunk contribution, in-place on g_yh
    attn_inter_kernel<<<dim3(NCH, BHx), 128>>>();

    // 3. Output projection -> fp32 out (256 tiles <= grid: one tile per CTA)
    {
        int tiles_n = Dx / TBN, tiles = (ROWSx / TBM) * tiles_n;    // 8, 256
        int grid = tiles < GEMM_GRID ? tiles : GEMM_GRID;
        gemm_tc_bias<float><<<grid, 256, TSMEM_TOTAL>>>(
            yh_ptr, wo_ptr, out_b, out, ROWSx, Dx, Dx, tiles_n, tiles);
    }
}

// round 14
// speedup vs baseline: 1.1212x; 1.1212x over previous
#include <cuda_runtime.h>
#include <cuda_fp16.h>
#include <cstdint>

#define Bx    2
#define Lx    2048
#define Dx    1024
#define Hx    16
#define DHx   64
#define CKx   64
#define NCH   32          // Lx / CKx
#define ROWSx 4096        // Bx * Lx
#define BHx   32          // Bx * Hx

// Scratch (device globals: no allocation allowed in kernel_launch)
__device__ __align__(16) __half g_qkvh[ROWSx * 3 * Dx];  // fp16 qkv (GEMM1 out)
__device__ float  g_M[BHx * NCH * DHx * DHx];            // per-chunk states (fp32)
__device__ __align__(16) __half g_Ph[BHx * NCH * DHx * DHx]; // exclusive prefix (fp16)
__device__ __align__(16) __half g_xh[ROWSx * Dx];        // fp16 x
__device__ __align__(16) __half g_wqh[3 * Dx * Dx];      // fp16 Wqkv_w
__device__ __align__(16) __half g_woh[Dx * Dx];          // fp16 out_w
__device__ __align__(16) __half g_yh[ROWSx * Dx];        // fp16 y (intra, then final)

// ============================================================================
// helpers (all non-"a" instructions: safe on plain sm_103 target)
// ============================================================================
__device__ __forceinline__ uint32_t smem_u32(const void* p) {
    uint32_t a;
    asm("{ .reg .u64 t; cvta.to.shared.u64 t, %1; cvt.u32.u64 %0, t; }"
        : "=r"(a) : "l"(p));
    return a;
}

#define CP16(dst, src) \
    asm volatile("cp.async.cg.shared.global [%0], [%1], 16;" :: "r"(dst), "l"(src) : "memory")
#define CP_COMMIT() asm volatile("cp.async.commit_group;" ::: "memory")
#define CP_WAIT0()  asm volatile("cp.async.wait_group 0;" ::: "memory")
#define CP_WAIT1()  asm volatile("cp.async.wait_group 1;" ::: "memory")

#define LDSM4(r0, r1, r2, r3, addr) \
    asm volatile("ldmatrix.sync.aligned.m8n8.x4.shared.b16 {%0,%1,%2,%3}, [%4];" \
                 : "=r"(r0), "=r"(r1), "=r"(r2), "=r"(r3) : "r"(addr))

#define LDSM4T(r0, r1, r2, r3, addr) \
    asm volatile("ldmatrix.sync.aligned.m8n8.x4.trans.shared.b16 {%0,%1,%2,%3}, [%4];" \
                 : "=r"(r0), "=r"(r1), "=r"(r2), "=r"(r3) : "r"(addr))

#define MMA_F16(d, a, b) \
    asm volatile("mma.sync.aligned.m16n8k16.row.col.f32.f16.f16.f32 " \
                 "{%0,%1,%2,%3}, {%4,%5,%6,%7}, {%8,%9}, {%0,%1,%2,%3};" \
                 : "+f"((d)[0]), "+f"((d)[1]), "+f"((d)[2]), "+f"((d)[3]) \
                 : "r"((a)[0]), "r"((a)[1]), "r"((a)[2]), "r"((a)[3]), \
                   "r"((b)[0]), "r"((b)[1]))

__device__ __forceinline__ void st2(float* p, float x, float y) {
    *(float2*)p = make_float2(x, y);
}
__device__ __forceinline__ void st2(__half* p, float x, float y) {
    *(__half2*)p = __floats2half2_rn(x, y);
}

// ============================================================================
// fused fp32 -> fp16 conversion of x, Wqkv_w, out_w (one launch)
// ============================================================================
#define NX4 (ROWSx * Dx / 4)        // 1048576
#define NQ4 (3 * Dx * Dx / 4)       // 786432
#define NO4 (Dx * Dx / 4)           // 262144

__global__ void __launch_bounds__(256) f2h_all_kernel(
    const float* __restrict__ x, const float* __restrict__ wq,
    const float* __restrict__ wo)
{
    int i = blockIdx.x * 256 + threadIdx.x;
    const float* src;
    __half* dst;
    int j;
    if (i < NX4) { src = x; dst = g_xh; j = i; }
    else if (i < NX4 + NQ4) { src = wq; dst = g_wqh; j = i - NX4; }
    else if (i < NX4 + NQ4 + NO4) { src = wo; dst = g_woh; j = i - NX4 - NQ4; }
    else return;
    float4 v = ((const float4*)src)[j];
    ((__half2*)dst)[2 * j + 0] = __floats2half2_rn(v.x, v.y);
    ((__half2*)dst)[2 * j + 1] = __floats2half2_rn(v.z, v.w);
}

// ============================================================================
// fp16 tensor-core GEMM (NT): C[M,N] = A[M,K] @ W[N,K]^T + bias[N]  (fp32 acc)
// CTA 128x128, BK=64 halves, 256 thr (8 warps 4x2, warp tile 32x64),
// 3-stage cp.async, 96KB smem, 2 CTAs/SM.  (R6/R9 proven shape. 2 CTAs x 256
// thr x 128 regs = the full RF/SM: this design point is closed.)
// ============================================================================
#define TBM 128
#define TBN 128
#define HBK 64
#define TSTG_BYTES (TBM * 128 + TBN * 128)           // 32768
#define TSMEM_TOTAL (3 * TSTG_BYTES)                 // 98304

__device__ __forceinline__ void tload(uint32_t stg, const __half* __restrict__ A,
                                      const __half* __restrict__ W, int K,
                                      int bm, int bn, int k0, int tid)
{
    #pragma unroll
    for (int j = 0; j < 4; j++) {
        int e = tid + j * 256;
        int r = e >> 3, c16 = e & 7;
        uint32_t dst = stg + (uint32_t)(r * 128 + ((c16 ^ (r & 7)) << 4));
        CP16(dst, A + (size_t)(bm + r) * K + k0 + c16 * 8);
    }
    #pragma unroll
    for (int j = 0; j < 4; j++) {
        int e = tid + j * 256;
        int r = e >> 3, c16 = e & 7;
        uint32_t dst = stg + 16384u + (uint32_t)(r * 128 + ((c16 ^ (r & 7)) << 4));
        CP16(dst, W + (size_t)(bn + r) * K + k0 + c16 * 8);
    }
}

template <typename OT>
__global__ void __launch_bounds__(256, 2) gemm_tc_bias(
    const __half* __restrict__ A, const __half* __restrict__ W,
    const float* __restrict__ bias, OT* __restrict__ C,
    int M, int N, int K)
{
    extern __shared__ char smem[];
    const uint32_t sb = smem_u32(smem);
    const int tid = threadIdx.x;
    const int lane = tid & 31, wid = tid >> 5;
    const int wm = wid & 3, wn = wid >> 2;
    const int bm = blockIdx.y * TBM;
    const int bn = blockIdx.x * TBN;
    const int NK = K / HBK;

    const int lrow = lane & 15;
    const int lkc  = lane >> 4;
    const int l7   = lrow & 7;

    uint32_t aRow[2], bRow[4];
    #pragma unroll
    for (int mt = 0; mt < 2; mt++) aRow[mt] = (uint32_t)((wm * 32 + mt * 16 + lrow) * 128);
    #pragma unroll
    for (int p = 0; p < 4; p++)    bRow[p] = (uint32_t)((wn * 64 + p * 16 + lrow) * 128);

    float d[2][8][4];
    #pragma unroll
    for (int mt = 0; mt < 2; mt++)
        #pragma unroll
        for (int nt = 0; nt < 8; nt++)
            #pragma unroll
            for (int i = 0; i < 4; i++) d[mt][nt][i] = 0.f;

    tload(sb, A, W, K, bm, bn, 0, tid);
    CP_COMMIT();
    tload(sb + TSTG_BYTES, A, W, K, bm, bn, HBK, tid);
    CP_COMMIT();

    int s0 = 0, s2 = 2;
    for (int i = 0; i < NK; i++) {
        CP_WAIT1();
        __syncthreads();
        if (i + 2 < NK)
            tload(sb + (uint32_t)(s2 * TSTG_BYTES), A, W, K, bm, bn, (i + 2) * HBK, tid);
        CP_COMMIT();

        const uint32_t sA = sb + (uint32_t)(s0 * TSTG_BYTES);
        const uint32_t sB = sA + 16384u;

        #pragma unroll
        for (int ks = 0; ks < 4; ks++) {
            const int kc = ks * 2;
            const uint32_t swz = (uint32_t)(((kc + lkc) ^ l7) << 4);

            uint32_t a[2][4];
            #pragma unroll
            for (int mt = 0; mt < 2; mt++)
                LDSM4(a[mt][0], a[mt][1], a[mt][2], a[mt][3], sA + aRow[mt] + swz);

            uint32_t b[8][2];
            #pragma unroll
            for (int p = 0; p < 4; p++) {
                uint32_t r0, r1, r2, r3;
                LDSM4(r0, r1, r2, r3, sB + bRow[p] + swz);
                b[2 * p][0] = r0; b[2 * p + 1][0] = r1;
                b[2 * p][1] = r2; b[2 * p + 1][1] = r3;
            }

            #pragma unroll
            for (int mt = 0; mt < 2; mt++)
                #pragma unroll
                for (int nt = 0; nt < 8; nt++)
                    MMA_F16(d[mt][nt], a[mt], b[nt]);
        }
        s0 = (s0 == 2) ? 0 : s0 + 1;
        s2 = (s2 == 2) ? 0 : s2 + 1;
    }

    const int erow = lane >> 2;
    const int ecol = (lane & 3) * 2;
    #pragma unroll
    for (int mt = 0; mt < 2; mt++) {
        const int r0 = bm + wm * 32 + mt * 16 + erow;
        #pragma unroll
        for (int nt = 0; nt < 8; nt++) {
            const int c = bn + wn * 64 + nt * 8 + ecol;
            float2 bv = *(const float2*)(bias + c);
            st2(C + (size_t)r0 * N + c, d[mt][nt][0] + bv.x, d[mt][nt][1] + bv.y);
            st2(C + (size_t)(r0 + 8) * N + c, d[mt][nt][2] + bv.x, d[mt][nt][3] + bv.y);
        }
    }
}

// ============================================================================
// Attention kernel A (fp16 MMA): per (bh, chunk) of 64 tokens:
//   S = tril(Q K^T) * 0.125 ;  Y_intra -> g_yh (fp16) ;  M = V^T K * 0.125 -> g_M
// 128 threads (4 warps), warp tile 16x64.
// ============================================================================
__global__ void __launch_bounds__(128) attn_intra_kernel()
{
    __shared__ __half sQ[64 * 64], sK[64 * 64], sV[64 * 64], sS[64 * 64];

    const int tid = threadIdx.x, lane = tid & 31, w = tid >> 5;
    const int chunk = blockIdx.x, bh = blockIdx.y;
    const int b = bh >> 4, h = bh & 15;

    const uint32_t q_s = smem_u32(sQ), k_s = smem_u32(sK);
    const uint32_t v_s = smem_u32(sV), s_s = smem_u32(sS);

    const __half* base = g_qkvh + (size_t)(b * Lx + chunk * CKx) * (3 * Dx) + h * DHx;
    #pragma unroll
    for (int j = 0; j < 4; j++) {
        int e = tid + j * 128;
        int r = e >> 3, c16 = e & 7;
        uint32_t off = (uint32_t)(r * 128 + ((c16 ^ (r & 7)) << 4));
        const __half* src = base + (size_t)r * (3 * Dx) + c16 * 8;
        CP16(q_s + off, src);
        CP16(k_s + off, src + Dx);
        CP16(v_s + off, src + 2 * Dx);
    }
    CP_COMMIT();
    CP_WAIT0();
    __syncthreads();

    const int lrow = lane & 15, lkc = lane >> 4, l7 = lrow & 7;
    const int erow = lane >> 2, ecol = (lane & 3) * 2;
    const uint32_t aRowOff = (uint32_t)((w * 16 + lrow) * 128);

    // ---- Phase 1: S = Q K^T (NT) ----
    float accS[8][4];
    #pragma unroll
    for (int nt = 0; nt < 8; nt++)
        #pragma unroll
        for (int i = 0; i < 4; i++) accS[nt][i] = 0.f;

    #pragma unroll
    for (int ks = 0; ks < 4; ks++) {
        const uint32_t swz = (uint32_t)(((ks * 2 + lkc) ^ l7) << 4);
        uint32_t a[4];
        LDSM4(a[0], a[1], a[2], a[3], q_s + aRowOff + swz);
        uint32_t bfr[8][2];
        #pragma unroll
        for (int p = 0; p < 4; p++) {
            uint32_t r0, r1, r2, r3;
            LDSM4(r0, r1, r2, r3, k_s + (uint32_t)((p * 16 + lrow) * 128) + swz);
            bfr[2 * p][0] = r0; bfr[2 * p + 1][0] = r1;
            bfr[2 * p][1] = r2; bfr[2 * p + 1][1] = r3;
        }
        #pragma unroll
        for (int nt = 0; nt < 8; nt++) MMA_F16(accS[nt], a, bfr[nt]);
    }

    // scale + causal mask + fp16 -> sS (swizzled)
    #pragma unroll
    for (int nt = 0; nt < 8; nt++) {
        const int i0 = w * 16 + erow, i1 = i0 + 8;
        const int j0 = nt * 8 + ecol;
        float s00 = (i0 >= j0)     ? accS[nt][0] * 0.125f : 0.f;
        float s01 = (i0 >= j0 + 1) ? accS[nt][1] * 0.125f : 0.f;
        float s10 = (i1 >= j0)     ? accS[nt][2] * 0.125f : 0.f;
        float s11 = (i1 >= j0 + 1) ? accS[nt][3] * 0.125f : 0.f;
        const uint32_t cb = (uint32_t)(j0 * 2);
        uint32_t o0 = (uint32_t)(i0 * 128) + (((cb >> 4) ^ (uint32_t)(i0 & 7)) << 4) + (cb & 15);
        uint32_t o1 = (uint32_t)(i1 * 128) + (((cb >> 4) ^ (uint32_t)(i1 & 7)) << 4) + (cb & 15);
        *(__half2*)((char*)sS + o0) = __floats2half2_rn(s00, s01);
        *(__half2*)((char*)sS + o1) = __floats2half2_rn(s10, s11);
    }
    __syncthreads();

    // ---- Phase 2: Y = S V (NN: B via ldmatrix.trans) -> fp16 g_yh ----
    float accY[8][4];
    #pragma unroll
    for (int nt = 0; nt < 8; nt++)
        #pragma unroll
        for (int i = 0; i < 4; i++) accY[nt][i] = 0.f;

    #pragma unroll
    for (int ks = 0; ks < 4; ks++) {
        const int kbase = ks * 16;
        const uint32_t swz = (uint32_t)(((ks * 2 + lkc) ^ l7) << 4);
        uint32_t a[4];
        LDSM4(a[0], a[1], a[2], a[3], s_s + aRowOff + swz);
        uint32_t bfr[8][2];
        #pragma unroll
        for (int nb = 0; nb < 4; nb++) {
            const int vr = kbase + lrow;
            const uint32_t c16 = (uint32_t)(nb * 2 + lkc);
            uint32_t r0, r1, r2, r3;
            LDSM4T(r0, r1, r2, r3, v_s + (uint32_t)(vr * 128) + ((c16 ^ (uint32_t)(vr & 7)) << 4));
            bfr[2 * nb][0] = r0; bfr[2 * nb][1] = r1;
            bfr[2 * nb + 1][0] = r2; bfr[2 * nb + 1][1] = r3;
        }
        #pragma unroll
        for (int nt = 0; nt < 8; nt++) MMA_F16(accY[nt], a, bfr[nt]);
    }

    __half* yb = g_yh + (size_t)(b * Lx + chunk * CKx) * Dx + h * DHx;
    #pragma unroll
    for (int nt = 0; nt < 8; nt++) {
        const int i0 = w * 16 + erow, j0 = nt * 8 + ecol;
        st2(yb + (size_t)i0 * Dx + j0, accY[nt][0], accY[nt][1]);
        st2(yb + (size_t)(i0 + 8) * Dx + j0, accY[nt][2], accY[nt][3]);
    }

    // ---- Phase 3: M = V^T K * 0.125 (A via trans, B via trans) ----
    float accM[8][4];
    #pragma unroll
    for (int nt = 0; nt < 8; nt++)
        #pragma unroll
        for (int i = 0; i < 4; i++) accM[nt][i] = 0.f;

    const int arow_lo = (lane & 7) + ((lane >> 4) << 3);
    const uint32_t ac16 = (uint32_t)(((w * 16) >> 3) + ((lane >> 3) & 1));

    #pragma unroll
    for (int ks = 0; ks < 4; ks++) {
        const int kbase = ks * 16;
        const int vr = kbase + arow_lo;
        uint32_t a[4];
        LDSM4T(a[0], a[1], a[2], a[3],
               v_s + (uint32_t)(vr * 128) + ((ac16 ^ (uint32_t)(vr & 7)) << 4));
        uint32_t bfr[8][2];
        #pragma unroll
        for (int nb = 0; nb < 4; nb++) {
            const int kr = kbase + lrow;
            const uint32_t c16 = (uint32_t)(nb * 2 + lkc);
            uint32_t r0, r1, r2, r3;
            LDSM4T(r0, r1, r2, r3, k_s + (uint32_t)(kr * 128) + ((c16 ^ (uint32_t)(kr & 7)) << 4));
            bfr[2 * nb][0] = r0; bfr[2 * nb][1] = r1;
            bfr[2 * nb + 1][0] = r2; bfr[2 * nb + 1][1] = r3;
        }
        #pragma unroll
        for (int nt = 0; nt < 8; nt++) MMA_F16(accM[nt], a, bfr[nt]);
    }

    float* Mb = g_M + (size_t)(bh * NCH + chunk) * (DHx * DHx);
    #pragma unroll
    for (int nt = 0; nt < 8; nt++) {
        const int a0 = w * 16 + erow, j0 = nt * 8 + ecol;
        st2(Mb + a0 * 64 + j0, accM[nt][0] * 0.125f, accM[nt][1] * 0.125f);
        st2(Mb + (a0 + 8) * 64 + j0, accM[nt][2] * 0.125f, accM[nt][3] * 0.125f);
    }
}

// ---------------------------------------------------------------------------
// Exclusive prefix over chunks, 2 threads per element strand (chunks 0-15 /
// 16-31), smem handoff of the midpoint total. Accumulation order identical to
// the single-thread version (bitwise-same results); 2x threads -> ~86% occ.
// ---------------------------------------------------------------------------
__global__ void __launch_bounds__(256) prefix_kernel()
{
    __shared__ float tot[128];

    const int tid = threadIdx.x;
    const int el = tid & 127;                 // element within block
    const int half = tid >> 7;                // 0: chunks 0-15, 1: chunks 16-31
    const int bh = blockIdx.y;
    const int e = blockIdx.x * 128 + el;      // 0..4095
    size_t base = (size_t)bh * NCH * (DHx * DHx) + e
                + (size_t)(half * 16) * (DHx * DHx);

    float m[16];
    #pragma unroll
    for (int c = 0; c < 16; c++)
        m[c] = g_M[base + (size_t)c * (DHx * DHx)];

    float pre[16];
    float acc = 0.f;
    #pragma unroll
    for (int c = 0; c < 16; c++) { pre[c] = acc; acc += m[c]; }

    if (half == 0) tot[el] = acc;
    __syncthreads();
    const float add = half ? tot[el] : 0.f;

    #pragma unroll
    for (int c = 0; c < 16; c++)
        g_Ph[base + (size_t)c * (DHx * DHx)] = __float2half_rn(add + pre[c]);
}

// ============================================================================
// Attention kernel C (fp16 MMA): y_final = y_intra(fp16, in g_yh) + Q P^T,
// in-place RMW on g_yh.  128 threads (4 warps), warp tile 16x64.
// ============================================================================
__global__ void __launch_bounds__(128) attn_inter_kernel()
{
    __shared__ __half sQ[64 * 64], sP[64 * 64];

    const int tid = threadIdx.x, lane = tid & 31, w = tid >> 5;
    const int chunk = blockIdx.x, bh = blockIdx.y;
    const int b = bh >> 4, h = bh & 15;

    const uint32_t q_s = smem_u32(sQ), p_s = smem_u32(sP);

    const __half* qbase = g_qkvh + (size_t)(b * Lx + chunk * CKx) * (3 * Dx) + h * DHx;
    const __half* Pbase = g_Ph + (size_t)(bh * NCH + chunk) * (DHx * DHx);
    #pragma unroll
    for (int j = 0; j < 4; j++) {
        int e = tid + j * 128;
        int r = e >> 3, c16 = e & 7;
        uint32_t off = (uint32_t)(r * 128 + ((c16 ^ (r & 7)) << 4));
        CP16(q_s + off, qbase + (size_t)r * (3 * Dx) + c16 * 8);
        CP16(p_s + off, Pbase + r * 64 + c16 * 8);
    }
    CP_COMMIT();
    CP_WAIT0();
    __syncthreads();

    const int lrow = lane & 15, lkc = lane >> 4, l7 = lrow & 7;
    const int erow = lane >> 2, ecol = (lane & 3) * 2;
    const uint32_t aRowOff = (uint32_t)((w * 16 + lrow) * 128);

    float acc[8][4];
    #pragma unroll
    for (int nt = 0; nt < 8; nt++)
        #pragma unroll
        for (int i = 0; i < 4; i++) acc[nt][i] = 0.f;

    #pragma unroll
    for (int ks = 0; ks < 4; ks++) {
        const uint32_t swz = (uint32_t)(((ks * 2 + lkc) ^ l7) << 4);
        uint32_t a[4];
        LDSM4(a[0], a[1], a[2], a[3], q_s + aRowOff + swz);
        uint32_t bfr[8][2];
        #pragma unroll
        for (int p = 0; p < 4; p++) {
            uint32_t r0, r1, r2, r3;
            LDSM4(r0, r1, r2, r3, p_s + (uint32_t)((p * 16 + lrow) * 128) + swz);
            bfr[2 * p][0] = r0; bfr[2 * p + 1][0] = r1;
            bfr[2 * p][1] = r2; bfr[2 * p + 1][1] = r3;
        }
        #pragma unroll
        for (int nt = 0; nt < 8; nt++) MMA_F16(acc[nt], a, bfr[nt]);
    }

    __half* yh = g_yh + (size_t)(b * Lx + chunk * CKx) * Dx + h * DHx;
    #pragma unroll
    for (int nt = 0; nt < 8; nt++) {
        const int i0 = w * 16 + erow, j0 = nt * 8 + ecol;
        float2 v0 = __half22float2(*(__half2*)(yh + (size_t)i0 * Dx + j0));
        float2 v1 = __half22float2(*(__half2*)(yh + (size_t)(i0 + 8) * Dx + j0));
        *(__half2*)(yh + (size_t)i0 * Dx + j0) =
            __floats2half2_rn(v0.x + acc[nt][0], v0.y + acc[nt][1]);
        *(__half2*)(yh + (size_t)(i0 + 8) * Dx + j0) =
            __floats2half2_rn(v1.x + acc[nt][2], v1.y + acc[nt][3]);
    }
}

// ---------------------------------------------------------------------------
extern "C" void kernel_launch(void* const* d_in, const int* in_sizes, int n_in,
                              void* d_out, int out_size)
{
    const float* x      = (const float*)d_in[0];   // [2,2048,1024]
    const float* Wqkv_w = (const float*)d_in[1];   // [3072,1024]
    const float* Wqkv_b = (const float*)d_in[2];   // [3072]
    const float* out_w  = (const float*)d_in[3];   // [1024,1024]
    const float* out_b  = (const float*)d_in[4];   // [1024]
    float* out = (float*)d_out;                    // [2,2048,1024]

    __half *qkvh_ptr, *xh_ptr, *wq_ptr, *wo_ptr, *yh_ptr;
    cudaGetSymbolAddress((void**)&qkvh_ptr, g_qkvh);
    cudaGetSymbolAddress((void**)&xh_ptr, g_xh);
    cudaGetSymbolAddress((void**)&wq_ptr, g_wqh);
    cudaGetSymbolAddress((void**)&wo_ptr, g_woh);
    cudaGetSymbolAddress((void**)&yh_ptr, g_yh);

    cudaFuncSetAttribute(gemm_tc_bias<__half>,
                         cudaFuncAttributeMaxDynamicSharedMemorySize, TSMEM_TOTAL);
    cudaFuncSetAttribute(gemm_tc_bias<float>,
                         cudaFuncAttributeMaxDynamicSharedMemorySize, TSMEM_TOTAL);

    // 0. fused fp16 conversion of GEMM operands (one launch)
    f2h_all_kernel<<<(NX4 + NQ4 + NO4 + 255) / 256, 256>>>(x, Wqkv_w, out_w);

    // 1. QKV projection -> fp16 qkv
    gemm_tc_bias<__half><<<dim3(3072 / TBN, ROWSx / TBM), 256, TSMEM_TOTAL>>>(
        xh_ptr, wq_ptr, Wqkv_b, qkvh_ptr, ROWSx, 3 * Dx, Dx);

    // 2a. Intra-chunk attention + per-chunk states -> g_yh (fp16), g_M
    attn_intra_kernel<<<dim3(NCH, BHx), 128>>>();

    // 2b. Exclusive prefix of states (2 threads/strand, smem midpoint handoff)
    prefix_kernel<<<dim3(32, BHx), 256>>>();

    // 2c. Inter-chunk contribution, in-place on g_yh
    attn_inter_kernel<<<dim3(NCH, BHx), 128>>>();

    // 3. Output projection -> fp32 out
    gemm_tc_bias<float><<<dim3(Dx / TBN, ROWSx / TBM), 256, TSMEM_TOTAL>>>(
        yh_ptr, wo_ptr, out_b, out, ROWSx, Dx, Dx);
}

// round 15
// speedup vs baseline: 1.1506x; 1.0263x over previous
#include <cuda_runtime.h>
#include <cuda_fp16.h>
#include <cstdint>

#define Bx    2
#define Lx    2048
#define Dx    1024
#define Hx    16
#define DHx   64
#define CKx   64
#define NCH   32          // Lx / CKx
#define ROWSx 4096        // Bx * Lx
#define BHx   32          // Bx * Hx

// Scratch (device globals: no allocation allowed in kernel_launch)
__device__ __align__(16) __half g_qkvh[ROWSx * 3 * Dx];  // fp16 qkv (GEMM1 out)
__device__ float  g_M[BHx * NCH * DHx * DHx];            // per-chunk states (fp32)
__device__ __align__(16) __half g_Ph[BHx * NCH * DHx * DHx]; // exclusive prefix (fp16)
__device__ __align__(16) __half g_xh[ROWSx * Dx];        // fp16 x
__device__ __align__(16) __half g_wqh[3 * Dx * Dx];      // fp16 Wqkv_w
__device__ __align__(16) __half g_woh[Dx * Dx];          // fp16 out_w
__device__ __align__(16) __half g_yh[ROWSx * Dx];        // fp16 y (final)

// ============================================================================
// helpers (all non-"a" instructions: safe on plain sm_103 target)
// ============================================================================
__device__ __forceinline__ uint32_t smem_u32(const void* p) {
    uint32_t a;
    asm("{ .reg .u64 t; cvta.to.shared.u64 t, %1; cvt.u32.u64 %0, t; }"
        : "=r"(a) : "l"(p));
    return a;
}

#define CP16(dst, src) \
    asm volatile("cp.async.cg.shared.global [%0], [%1], 16;" :: "r"(dst), "l"(src) : "memory")
#define CP_COMMIT() asm volatile("cp.async.commit_group;" ::: "memory")
#define CP_WAIT0()  asm volatile("cp.async.wait_group 0;" ::: "memory")
#define CP_WAIT1()  asm volatile("cp.async.wait_group 1;" ::: "memory")

#define LDSM4(r0, r1, r2, r3, addr) \
    asm volatile("ldmatrix.sync.aligned.m8n8.x4.shared.b16 {%0,%1,%2,%3}, [%4];" \
                 : "=r"(r0), "=r"(r1), "=r"(r2), "=r"(r3) : "r"(addr))

#define LDSM4T(r0, r1, r2, r3, addr) \
    asm volatile("ldmatrix.sync.aligned.m8n8.x4.trans.shared.b16 {%0,%1,%2,%3}, [%4];" \
                 : "=r"(r0), "=r"(r1), "=r"(r2), "=r"(r3) : "r"(addr))

#define MMA_F16(d, a, b) \
    asm volatile("mma.sync.aligned.m16n8k16.row.col.f32.f16.f16.f32 " \
                 "{%0,%1,%2,%3}, {%4,%5,%6,%7}, {%8,%9}, {%0,%1,%2,%3};" \
                 : "+f"((d)[0]), "+f"((d)[1]), "+f"((d)[2]), "+f"((d)[3]) \
                 : "r"((a)[0]), "r"((a)[1]), "r"((a)[2]), "r"((a)[3]), \
                   "r"((b)[0]), "r"((b)[1]))

__device__ __forceinline__ void st2(float* p, float x, float y) {
    *(float2*)p = make_float2(x, y);
}
__device__ __forceinline__ void st2(__half* p, float x, float y) {
    *(__half2*)p = __floats2half2_rn(x, y);
}

// ============================================================================
// fused fp32 -> fp16 conversion of x, Wqkv_w, out_w (one launch)
// ============================================================================
#define NX4 (ROWSx * Dx / 4)        // 1048576
#define NQ4 (3 * Dx * Dx / 4)       // 786432
#define NO4 (Dx * Dx / 4)           // 262144

__global__ void __launch_bounds__(256) f2h_all_kernel(
    const float* __restrict__ x, const float* __restrict__ wq,
    const float* __restrict__ wo)
{
    int i = blockIdx.x * 256 + threadIdx.x;
    const float* src;
    __half* dst;
    int j;
    if (i < NX4) { src = x; dst = g_xh; j = i; }
    else if (i < NX4 + NQ4) { src = wq; dst = g_wqh; j = i - NX4; }
    else if (i < NX4 + NQ4 + NO4) { src = wo; dst = g_woh; j = i - NX4 - NQ4; }
    else return;
    float4 v = ((const float4*)src)[j];
    ((__half2*)dst)[2 * j + 0] = __floats2half2_rn(v.x, v.y);
    ((__half2*)dst)[2 * j + 1] = __floats2half2_rn(v.z, v.w);
}

// ============================================================================
// fp16 tensor-core GEMM (NT): C[M,N] = A[M,K] @ W[N,K]^T + bias[N]  (fp32 acc)
// CTA 128x128, BK=64 halves, 256 thr (8 warps 4x2, warp tile 32x64),
// 3-stage cp.async, 96KB smem, 2 CTAs/SM.  (R6/R14 proven shape; closed.)
// ============================================================================
#define TBM 128
#define TBN 128
#define HBK 64
#define TSTG_BYTES (TBM * 128 + TBN * 128)           // 32768
#define TSMEM_TOTAL (3 * TSTG_BYTES)                 // 98304

__device__ __forceinline__ void tload(uint32_t stg, const __half* __restrict__ A,
                                      const __half* __restrict__ W, int K,
                                      int bm, int bn, int k0, int tid)
{
    #pragma unroll
    for (int j = 0; j < 4; j++) {
        int e = tid + j * 256;
        int r = e >> 3, c16 = e & 7;
        uint32_t dst = stg + (uint32_t)(r * 128 + ((c16 ^ (r & 7)) << 4));
        CP16(dst, A + (size_t)(bm + r) * K + k0 + c16 * 8);
    }
    #pragma unroll
    for (int j = 0; j < 4; j++) {
        int e = tid + j * 256;
        int r = e >> 3, c16 = e & 7;
        uint32_t dst = stg + 16384u + (uint32_t)(r * 128 + ((c16 ^ (r & 7)) << 4));
        CP16(dst, W + (size_t)(bn + r) * K + k0 + c16 * 8);
    }
}

template <typename OT>
__global__ void __launch_bounds__(256, 2) gemm_tc_bias(
    const __half* __restrict__ A, const __half* __restrict__ W,
    const float* __restrict__ bias, OT* __restrict__ C,
    int M, int N, int K)
{
    extern __shared__ char smem[];
    const uint32_t sb = smem_u32(smem);
    const int tid = threadIdx.x;
    const int lane = tid & 31, wid = tid >> 5;
    const int wm = wid & 3, wn = wid >> 2;
    const int bm = blockIdx.y * TBM;
    const int bn = blockIdx.x * TBN;
    const int NK = K / HBK;

    const int lrow = lane & 15;
    const int lkc  = lane >> 4;
    const int l7   = lrow & 7;

    uint32_t aRow[2], bRow[4];
    #pragma unroll
    for (int mt = 0; mt < 2; mt++) aRow[mt] = (uint32_t)((wm * 32 + mt * 16 + lrow) * 128);
    #pragma unroll
    for (int p = 0; p < 4; p++)    bRow[p] = (uint32_t)((wn * 64 + p * 16 + lrow) * 128);

    float d[2][8][4];
    #pragma unroll
    for (int mt = 0; mt < 2; mt++)
        #pragma unroll
        for (int nt = 0; nt < 8; nt++)
            #pragma unroll
            for (int i = 0; i < 4; i++) d[mt][nt][i] = 0.f;

    tload(sb, A, W, K, bm, bn, 0, tid);
    CP_COMMIT();
    tload(sb + TSTG_BYTES, A, W, K, bm, bn, HBK, tid);
    CP_COMMIT();

    int s0 = 0, s2 = 2;
    for (int i = 0; i < NK; i++) {
        CP_WAIT1();
        __syncthreads();
        if (i + 2 < NK)
            tload(sb + (uint32_t)(s2 * TSTG_BYTES), A, W, K, bm, bn, (i + 2) * HBK, tid);
        CP_COMMIT();

        const uint32_t sA = sb + (uint32_t)(s0 * TSTG_BYTES);
        const uint32_t sB = sA + 16384u;

        #pragma unroll
        for (int ks = 0; ks < 4; ks++) {
            const int kc = ks * 2;
            const uint32_t swz = (uint32_t)(((kc + lkc) ^ l7) << 4);

            uint32_t a[2][4];
            #pragma unroll
            for (int mt = 0; mt < 2; mt++)
                LDSM4(a[mt][0], a[mt][1], a[mt][2], a[mt][3], sA + aRow[mt] + swz);

            uint32_t b[8][2];
            #pragma unroll
            for (int p = 0; p < 4; p++) {
                uint32_t r0, r1, r2, r3;
                LDSM4(r0, r1, r2, r3, sB + bRow[p] + swz);
                b[2 * p][0] = r0; b[2 * p + 1][0] = r1;
                b[2 * p][1] = r2; b[2 * p + 1][1] = r3;
            }

            #pragma unroll
            for (int mt = 0; mt < 2; mt++)
                #pragma unroll
                for (int nt = 0; nt < 8; nt++)
                    MMA_F16(d[mt][nt], a[mt], b[nt]);
        }
        s0 = (s0 == 2) ? 0 : s0 + 1;
        s2 = (s2 == 2) ? 0 : s2 + 1;
    }

    const int erow = lane >> 2;
    const int ecol = (lane & 3) * 2;
    #pragma unroll
    for (int mt = 0; mt < 2; mt++) {
        const int r0 = bm + wm * 32 + mt * 16 + erow;
        #pragma unroll
        for (int nt = 0; nt < 8; nt++) {
            const int c = bn + wn * 64 + nt * 8 + ecol;
            float2 bv = *(const float2*)(bias + c);
            st2(C + (size_t)r0 * N + c, d[mt][nt][0] + bv.x, d[mt][nt][1] + bv.y);
            st2(C + (size_t)(r0 + 8) * N + c, d[mt][nt][2] + bv.x, d[mt][nt][3] + bv.y);
        }
    }
}

// ============================================================================
// Attention A1 (state kernel): per (bh, chunk): M = V^T K * 0.125 -> g_M.
// Loads only K,V. One MMA phase. 128 threads (4 warps), warp tile 16x64.
// ============================================================================
__global__ void __launch_bounds__(128) attn_state_kernel()
{
    __shared__ __half sK[64 * 64], sV[64 * 64];

    const int tid = threadIdx.x, lane = tid & 31, w = tid >> 5;
    const int chunk = blockIdx.x, bh = blockIdx.y;
    const int b = bh >> 4, h = bh & 15;

    const uint32_t k_s = smem_u32(sK), v_s = smem_u32(sV);

    const __half* base = g_qkvh + (size_t)(b * Lx + chunk * CKx) * (3 * Dx) + h * DHx;
    #pragma unroll
    for (int j = 0; j < 4; j++) {
        int e = tid + j * 128;
        int r = e >> 3, c16 = e & 7;
        uint32_t off = (uint32_t)(r * 128 + ((c16 ^ (r & 7)) << 4));
        const __half* src = base + (size_t)r * (3 * Dx) + c16 * 8;
        CP16(k_s + off, src + Dx);
        CP16(v_s + off, src + 2 * Dx);
    }
    CP_COMMIT();
    CP_WAIT0();
    __syncthreads();

    const int lrow = lane & 15, lkc = lane >> 4;
    const int erow = lane >> 2, ecol = (lane & 3) * 2;

    float accM[8][4];
    #pragma unroll
    for (int nt = 0; nt < 8; nt++)
        #pragma unroll
        for (int i = 0; i < 4; i++) accM[nt][i] = 0.f;

    const int arow_lo = (lane & 7) + ((lane >> 4) << 3);
    const uint32_t ac16 = (uint32_t)(((w * 16) >> 3) + ((lane >> 3) & 1));

    #pragma unroll
    for (int ks = 0; ks < 4; ks++) {
        const int kbase = ks * 16;
        const int vr = kbase + arow_lo;
        uint32_t a[4];
        LDSM4T(a[0], a[1], a[2], a[3],
               v_s + (uint32_t)(vr * 128) + ((ac16 ^ (uint32_t)(vr & 7)) << 4));
        uint32_t bfr[8][2];
        #pragma unroll
        for (int nb = 0; nb < 4; nb++) {
            const int kr = kbase + lrow;
            const uint32_t c16 = (uint32_t)(nb * 2 + lkc);
            uint32_t r0, r1, r2, r3;
            LDSM4T(r0, r1, r2, r3, k_s + (uint32_t)(kr * 128) + ((c16 ^ (uint32_t)(kr & 7)) << 4));
            bfr[2 * nb][0] = r0; bfr[2 * nb][1] = r1;
            bfr[2 * nb + 1][0] = r2; bfr[2 * nb + 1][1] = r3;
        }
        #pragma unroll
        for (int nt = 0; nt < 8; nt++) MMA_F16(accM[nt], a, bfr[nt]);
    }

    float* Mb = g_M + (size_t)(bh * NCH + chunk) * (DHx * DHx);
    #pragma unroll
    for (int nt = 0; nt < 8; nt++) {
        const int a0 = w * 16 + erow, j0 = nt * 8 + ecol;
        st2(Mb + a0 * 64 + j0, accM[nt][0] * 0.125f, accM[nt][1] * 0.125f);
        st2(Mb + (a0 + 8) * 64 + j0, accM[nt][2] * 0.125f, accM[nt][3] * 0.125f);
    }
}

// ---------------------------------------------------------------------------
// Exclusive prefix over chunks, 2 threads per element strand (R14 winner).
// ---------------------------------------------------------------------------
__global__ void __launch_bounds__(256) prefix_kernel()
{
    __shared__ float tot[128];

    const int tid = threadIdx.x;
    const int el = tid & 127;
    const int half = tid >> 7;
    const int bh = blockIdx.y;
    const int e = blockIdx.x * 128 + el;
    size_t base = (size_t)bh * NCH * (DHx * DHx) + e
                + (size_t)(half * 16) * (DHx * DHx);

    float m[16];
    #pragma unroll
    for (int c = 0; c < 16; c++)
        m[c] = g_M[base + (size_t)c * (DHx * DHx)];

    float pre[16];
    float acc = 0.f;
    #pragma unroll
    for (int c = 0; c < 16; c++) { pre[c] = acc; acc += m[c]; }

    if (half == 0) tot[el] = acc;
    __syncthreads();
    const float add = half ? tot[el] : 0.f;

    #pragma unroll
    for (int c = 0; c < 16; c++)
        g_Ph[base + (size_t)c * (DHx * DHx)] = __float2half_rn(add + pre[c]);
}

// ============================================================================
// Attention A2 (fused output kernel): per (bh, chunk):
//   phase 1: accS = Q K^T  AND  accY = Q P^T  (shared Q fragments!)
//   phase 2: accY += tril(accS)*0.125 (via fp16 smem) @ V
//   y -> g_yh fp16 (single store, no RMW, one fp16 rounding).
// 128 threads (4 warps), warp tile 16x64.
// ============================================================================
__global__ void __launch_bounds__(128) attn_fused_kernel()
{
    __shared__ __half sQ[64 * 64], sK[64 * 64], sV[64 * 64], sP[64 * 64], sS[64 * 64];

    const int tid = threadIdx.x, lane = tid & 31, w = tid >> 5;
    const int chunk = blockIdx.x, bh = blockIdx.y;
    const int b = bh >> 4, h = bh & 15;

    const uint32_t q_s = smem_u32(sQ), k_s = smem_u32(sK);
    const uint32_t v_s = smem_u32(sV), p_s = smem_u32(sP);
    const uint32_t s_s = smem_u32(sS);

    const __half* base = g_qkvh + (size_t)(b * Lx + chunk * CKx) * (3 * Dx) + h * DHx;
    const __half* Pbase = g_Ph + (size_t)(bh * NCH + chunk) * (DHx * DHx);
    #pragma unroll
    for (int j = 0; j < 4; j++) {
        int e = tid + j * 128;
        int r = e >> 3, c16 = e & 7;
        uint32_t off = (uint32_t)(r * 128 + ((c16 ^ (r & 7)) << 4));
        const __half* src = base + (size_t)r * (3 * Dx) + c16 * 8;
        CP16(q_s + off, src);
        CP16(k_s + off, src + Dx);
        CP16(v_s + off, src + 2 * Dx);
        CP16(p_s + off, Pbase + r * 64 + c16 * 8);
    }
    CP_COMMIT();
    CP_WAIT0();
    __syncthreads();

    const int lrow = lane & 15, lkc = lane >> 4, l7 = lrow & 7;
    const int erow = lane >> 2, ecol = (lane & 3) * 2;
    const uint32_t aRowOff = (uint32_t)((w * 16 + lrow) * 128);

    // ---- Phase 1: accS = Q K^T ; accY = Q P^T (Q frags shared per ks) ----
    float accS[8][4], accY[8][4];
    #pragma unroll
    for (int nt = 0; nt < 8; nt++)
        #pragma unroll
        for (int i = 0; i < 4; i++) { accS[nt][i] = 0.f; accY[nt][i] = 0.f; }

    #pragma unroll
    for (int ks = 0; ks < 4; ks++) {
        const uint32_t swz = (uint32_t)(((ks * 2 + lkc) ^ l7) << 4);
        uint32_t a[4];
        LDSM4(a[0], a[1], a[2], a[3], q_s + aRowOff + swz);

        uint32_t bk[8][2];
        #pragma unroll
        for (int p = 0; p < 4; p++) {
            uint32_t r0, r1, r2, r3;
            LDSM4(r0, r1, r2, r3, k_s + (uint32_t)((p * 16 + lrow) * 128) + swz);
            bk[2 * p][0] = r0; bk[2 * p + 1][0] = r1;
            bk[2 * p][1] = r2; bk[2 * p + 1][1] = r3;
        }
        #pragma unroll
        for (int nt = 0; nt < 8; nt++) MMA_F16(accS[nt], a, bk[nt]);

        uint32_t bp[8][2];
        #pragma unroll
        for (int p = 0; p < 4; p++) {
            uint32_t r0, r1, r2, r3;
            LDSM4(r0, r1, r2, r3, p_s + (uint32_t)((p * 16 + lrow) * 128) + swz);
            bp[2 * p][0] = r0; bp[2 * p + 1][0] = r1;
            bp[2 * p][1] = r2; bp[2 * p + 1][1] = r3;
        }
        #pragma unroll
        for (int nt = 0; nt < 8; nt++) MMA_F16(accY[nt], a, bp[nt]);
    }

    // scale + causal mask + fp16 -> sS (swizzled)
    #pragma unroll
    for (int nt = 0; nt < 8; nt++) {
        const int i0 = w * 16 + erow, i1 = i0 + 8;
        const int j0 = nt * 8 + ecol;
        float s00 = (i0 >= j0)     ? accS[nt][0] * 0.125f : 0.f;
        float s01 = (i0 >= j0 + 1) ? accS[nt][1] * 0.125f : 0.f;
        float s10 = (i1 >= j0)     ? accS[nt][2] * 0.125f : 0.f;
        float s11 = (i1 >= j0 + 1) ? accS[nt][3] * 0.125f : 0.f;
        const uint32_t cb = (uint32_t)(j0 * 2);
        uint32_t o0 = (uint32_t)(i0 * 128) + (((cb >> 4) ^ (uint32_t)(i0 & 7)) << 4) + (cb & 15);
        uint32_t o1 = (uint32_t)(i1 * 128) + (((cb >> 4) ^ (uint32_t)(i1 & 7)) << 4) + (cb & 15);
        *(__half2*)((char*)sS + o0) = __floats2half2_rn(s00, s01);
        *(__half2*)((char*)sS + o1) = __floats2half2_rn(s10, s11);
    }
    __syncthreads();

    // ---- Phase 2: accY += S V (NN: B via ldmatrix.trans) ----
    #pragma unroll
    for (int ks = 0; ks < 4; ks++) {
        const int kbase = ks * 16;
        const uint32_t swz = (uint32_t)(((ks * 2 + lkc) ^ l7) << 4);
        uint32_t a[4];
        LDSM4(a[0], a[1], a[2], a[3], s_s + aRowOff + swz);
        uint32_t bfr[8][2];
        #pragma unroll
        for (int nb = 0; nb < 4; nb++) {
            const int vr = kbase + lrow;
            const uint32_t c16 = (uint32_t)(nb * 2 + lkc);
            uint32_t r0, r1, r2, r3;
            LDSM4T(r0, r1, r2, r3, v_s + (uint32_t)(vr * 128) + ((c16 ^ (uint32_t)(vr & 7)) << 4));
            bfr[2 * nb][0] = r0; bfr[2 * nb][1] = r1;
            bfr[2 * nb + 1][0] = r2; bfr[2 * nb + 1][1] = r3;
        }
        #pragma unroll
        for (int nt = 0; nt < 8; nt++) MMA_F16(accY[nt], a, bfr[nt]);
    }

    __half* yb = g_yh + (size_t)(b * Lx + chunk * CKx) * Dx + h * DHx;
    #pragma unroll
    for (int nt = 0; nt < 8; nt++) {
        const int i0 = w * 16 + erow, j0 = nt * 8 + ecol;
        st2(yb + (size_t)i0 * Dx + j0, accY[nt][0], accY[nt][1]);
        st2(yb + (size_t)(i0 + 8) * Dx + j0, accY[nt][2], accY[nt][3]);
    }
}

// ---------------------------------------------------------------------------
extern "C" void kernel_launch(void* const* d_in, const int* in_sizes, int n_in,
                              void* d_out, int out_size)
{
    const float* x      = (const float*)d_in[0];   // [2,2048,1024]
    const float* Wqkv_w = (const float*)d_in[1];   // [3072,1024]
    const float* Wqkv_b = (const float*)d_in[2];   // [3072]
    const float* out_w  = (const float*)d_in[3];   // [1024,1024]
    const float* out_b  = (const float*)d_in[4];   // [1024]
    float* out = (float*)d_out;                    // [2,2048,1024]

    __half *qkvh_ptr, *xh_ptr, *wq_ptr, *wo_ptr, *yh_ptr;
    cudaGetSymbolAddress((void**)&qkvh_ptr, g_qkvh);
    cudaGetSymbolAddress((void**)&xh_ptr, g_xh);
    cudaGetSymbolAddress((void**)&wq_ptr, g_wqh);
    cudaGetSymbolAddress((void**)&wo_ptr, g_woh);
    cudaGetSymbolAddress((void**)&yh_ptr, g_yh);

    cudaFuncSetAttribute(gemm_tc_bias<__half>,
                         cudaFuncAttributeMaxDynamicSharedMemorySize, TSMEM_TOTAL);
    cudaFuncSetAttribute(gemm_tc_bias<float>,
                         cudaFuncAttributeMaxDynamicSharedMemorySize, TSMEM_TOTAL);

    // 0. fused fp16 conversion of GEMM operands (one launch)
    f2h_all_kernel<<<(NX4 + NQ4 + NO4 + 255) / 256, 256>>>(x, Wqkv_w, out_w);

    // 1. QKV projection -> fp16 qkv
    gemm_tc_bias<__half><<<dim3(3072 / TBN, ROWSx / TBM), 256, TSMEM_TOTAL>>>(
        xh_ptr, wq_ptr, Wqkv_b, qkvh_ptr, ROWSx, 3 * Dx, Dx);

    // 2a. Per-chunk states M = V^T K (light, one MMA phase)
    attn_state_kernel<<<dim3(NCH, BHx), 128>>>();

    // 2b. Exclusive prefix of states -> fp16 P
    prefix_kernel<<<dim3(32, BHx), 256>>>();

    // 2c. Fused output: y = tril(QK^T)*scale @ V + Q P^T -> g_yh (one store)
    attn_fused_kernel<<<dim3(NCH, BHx), 128>>>();

    // 3. Output projection -> fp32 out
    gemm_tc_bias<float><<<dim3(Dx / TBN, ROWSx / TBM), 256, TSMEM_TOTAL>>>(
        yh_ptr, wo_ptr, out_b, out, ROWSx, Dx, Dx);
}

// round 16
// speedup vs baseline: 1.1691x; 1.0160x over previous
#include <cuda_runtime.h>
#include <cuda_fp16.h>
#include <cstdint>

#define Bx    2
#define Lx    2048
#define Dx    1024
#define Hx    16
#define DHx   64
#define CKx   64
#define NCH   32          // Lx / CKx
#define ROWSx 4096        // Bx * Lx
#define BHx   32          // Bx * Hx

// Scratch (device globals: no allocation allowed in kernel_launch)
__device__ __align__(16) __half g_qkvh[ROWSx * 3 * Dx];  // fp16 qkv (GEMM1 out)
__device__ __align__(16) __half g_Mh[BHx * NCH * DHx * DHx]; // per-chunk states (fp16)
__device__ __align__(16) __half g_Ph[BHx * NCH * DHx * DHx]; // exclusive prefix (fp16)
__device__ __align__(16) __half g_xh[ROWSx * Dx];        // fp16 x
__device__ __align__(16) __half g_wqh[3 * Dx * Dx];      // fp16 Wqkv_w
__device__ __align__(16) __half g_woh[Dx * Dx];          // fp16 out_w
__device__ __align__(16) __half g_yh[ROWSx * Dx];        // fp16 y (final)

// ============================================================================
// helpers (all non-"a" instructions: safe on plain sm_103 target)
// ============================================================================
__device__ __forceinline__ uint32_t smem_u32(const void* p) {
    uint32_t a;
    asm("{ .reg .u64 t; cvta.to.shared.u64 t, %1; cvt.u32.u64 %0, t; }"
        : "=r"(a) : "l"(p));
    return a;
}

#define CP16(dst, src) \
    asm volatile("cp.async.cg.shared.global [%0], [%1], 16;" :: "r"(dst), "l"(src) : "memory")
#define CP_COMMIT() asm volatile("cp.async.commit_group;" ::: "memory")
#define CP_WAIT0()  asm volatile("cp.async.wait_group 0;" ::: "memory")
#define CP_WAIT1()  asm volatile("cp.async.wait_group 1;" ::: "memory")

#define LDSM4(r0, r1, r2, r3, addr) \
    asm volatile("ldmatrix.sync.aligned.m8n8.x4.shared.b16 {%0,%1,%2,%3}, [%4];" \
                 : "=r"(r0), "=r"(r1), "=r"(r2), "=r"(r3) : "r"(addr))

#define LDSM4T(r0, r1, r2, r3, addr) \
    asm volatile("ldmatrix.sync.aligned.m8n8.x4.trans.shared.b16 {%0,%1,%2,%3}, [%4];" \
                 : "=r"(r0), "=r"(r1), "=r"(r2), "=r"(r3) : "r"(addr))

#define MMA_F16(d, a, b) \
    asm volatile("mma.sync.aligned.m16n8k16.row.col.f32.f16.f16.f32 " \
                 "{%0,%1,%2,%3}, {%4,%5,%6,%7}, {%8,%9}, {%0,%1,%2,%3};" \
                 : "+f"((d)[0]), "+f"((d)[1]), "+f"((d)[2]), "+f"((d)[3]) \
                 : "r"((a)[0]), "r"((a)[1]), "r"((a)[2]), "r"((a)[3]), \
                   "r"((b)[0]), "r"((b)[1]))

__device__ __forceinline__ void st2(float* p, float x, float y) {
    *(float2*)p = make_float2(x, y);
}
__device__ __forceinline__ void st2(__half* p, float x, float y) {
    *(__half2*)p = __floats2half2_rn(x, y);
}

// masked+scaled pack of two fp32 S values into one fp16x2 A-fragment register
__device__ __forceinline__ uint32_t pack_mask(float x, float y, int i, int j) {
    float sx = (i >= j)     ? x * 0.125f : 0.f;
    float sy = (i >= j + 1) ? y * 0.125f : 0.f;
    __half2 h = __floats2half2_rn(sx, sy);
    return *(uint32_t*)&h;
}

// ============================================================================
// fused fp32 -> fp16 conversion of x, Wqkv_w, out_w (one launch)
// ============================================================================
#define NX4 (ROWSx * Dx / 4)        // 1048576
#define NQ4 (3 * Dx * Dx / 4)       // 786432
#define NO4 (Dx * Dx / 4)           // 262144

__global__ void __launch_bounds__(256) f2h_all_kernel(
    const float* __restrict__ x, const float* __restrict__ wq,
    const float* __restrict__ wo)
{
    int i = blockIdx.x * 256 + threadIdx.x;
    const float* src;
    __half* dst;
    int j;
    if (i < NX4) { src = x; dst = g_xh; j = i; }
    else if (i < NX4 + NQ4) { src = wq; dst = g_wqh; j = i - NX4; }
    else if (i < NX4 + NQ4 + NO4) { src = wo; dst = g_woh; j = i - NX4 - NQ4; }
    else return;
    float4 v = ((const float4*)src)[j];
    ((__half2*)dst)[2 * j + 0] = __floats2half2_rn(v.x, v.y);
    ((__half2*)dst)[2 * j + 1] = __floats2half2_rn(v.z, v.w);
}

// ============================================================================
// fp16 tensor-core GEMM (NT): C[M,N] = A[M,K] @ W[N,K]^T + bias[N]  (fp32 acc)
// CTA 128x128, BK=64 halves, 256 thr (8 warps 4x2, warp tile 32x64),
// 3-stage cp.async, 96KB smem, 2 CTAs/SM.  (R6/R14 proven shape; closed.)
// ============================================================================
#define TBM 128
#define TBN 128
#define HBK 64
#define TSTG_BYTES (TBM * 128 + TBN * 128)           // 32768
#define TSMEM_TOTAL (3 * TSTG_BYTES)                 // 98304

__device__ __forceinline__ void tload(uint32_t stg, const __half* __restrict__ A,
                                      const __half* __restrict__ W, int K,
                                      int bm, int bn, int k0, int tid)
{
    #pragma unroll
    for (int j = 0; j < 4; j++) {
        int e = tid + j * 256;
        int r = e >> 3, c16 = e & 7;
        uint32_t dst = stg + (uint32_t)(r * 128 + ((c16 ^ (r & 7)) << 4));
        CP16(dst, A + (size_t)(bm + r) * K + k0 + c16 * 8);
    }
    #pragma unroll
    for (int j = 0; j < 4; j++) {
        int e = tid + j * 256;
        int r = e >> 3, c16 = e & 7;
        uint32_t dst = stg + 16384u + (uint32_t)(r * 128 + ((c16 ^ (r & 7)) << 4));
        CP16(dst, W + (size_t)(bn + r) * K + k0 + c16 * 8);
    }
}

template <typename OT>
__global__ void __launch_bounds__(256, 2) gemm_tc_bias(
    const __half* __restrict__ A, const __half* __restrict__ W,
    const float* __restrict__ bias, OT* __restrict__ C,
    int M, int N, int K)
{
    extern __shared__ char smem[];
    const uint32_t sb = smem_u32(smem);
    const int tid = threadIdx.x;
    const int lane = tid & 31, wid = tid >> 5;
    const int wm = wid & 3, wn = wid >> 2;
    const int bm = blockIdx.y * TBM;
    const int bn = blockIdx.x * TBN;
    const int NK = K / HBK;

    const int lrow = lane & 15;
    const int lkc  = lane >> 4;
    const int l7   = lrow & 7;

    uint32_t aRow[2], bRow[4];
    #pragma unroll
    for (int mt = 0; mt < 2; mt++) aRow[mt] = (uint32_t)((wm * 32 + mt * 16 + lrow) * 128);
    #pragma unroll
    for (int p = 0; p < 4; p++)    bRow[p] = (uint32_t)((wn * 64 + p * 16 + lrow) * 128);

    float d[2][8][4];
    #pragma unroll
    for (int mt = 0; mt < 2; mt++)
        #pragma unroll
        for (int nt = 0; nt < 8; nt++)
            #pragma unroll
            for (int i = 0; i < 4; i++) d[mt][nt][i] = 0.f;

    tload(sb, A, W, K, bm, bn, 0, tid);
    CP_COMMIT();
    tload(sb + TSTG_BYTES, A, W, K, bm, bn, HBK, tid);
    CP_COMMIT();

    int s0 = 0, s2 = 2;
    for (int i = 0; i < NK; i++) {
        CP_WAIT1();
        __syncthreads();
        if (i + 2 < NK)
            tload(sb + (uint32_t)(s2 * TSTG_BYTES), A, W, K, bm, bn, (i + 2) * HBK, tid);
        CP_COMMIT();

        const uint32_t sA = sb + (uint32_t)(s0 * TSTG_BYTES);
        const uint32_t sB = sA + 16384u;

        #pragma unroll
        for (int ks = 0; ks < 4; ks++) {
            const int kc = ks * 2;
            const uint32_t swz = (uint32_t)(((kc + lkc) ^ l7) << 4);

            uint32_t a[2][4];
            #pragma unroll
            for (int mt = 0; mt < 2; mt++)
                LDSM4(a[mt][0], a[mt][1], a[mt][2], a[mt][3], sA + aRow[mt] + swz);

            uint32_t b[8][2];
            #pragma unroll
            for (int p = 0; p < 4; p++) {
                uint32_t r0, r1, r2, r3;
                LDSM4(r0, r1, r2, r3, sB + bRow[p] + swz);
                b[2 * p][0] = r0; b[2 * p + 1][0] = r1;
                b[2 * p][1] = r2; b[2 * p + 1][1] = r3;
            }

            #pragma unroll
            for (int mt = 0; mt < 2; mt++)
                #pragma unroll
                for (int nt = 0; nt < 8; nt++)
                    MMA_F16(d[mt][nt], a[mt], b[nt]);
        }
        s0 = (s0 == 2) ? 0 : s0 + 1;
        s2 = (s2 == 2) ? 0 : s2 + 1;
    }

    const int erow = lane >> 2;
    const int ecol = (lane & 3) * 2;
    #pragma unroll
    for (int mt = 0; mt < 2; mt++) {
        const int r0 = bm + wm * 32 + mt * 16 + erow;
        #pragma unroll
        for (int nt = 0; nt < 8; nt++) {
            const int c = bn + wn * 64 + nt * 8 + ecol;
            float2 bv = *(const float2*)(bias + c);
            st2(C + (size_t)r0 * N + c, d[mt][nt][0] + bv.x, d[mt][nt][1] + bv.y);
            st2(C + (size_t)(r0 + 8) * N + c, d[mt][nt][2] + bv.x, d[mt][nt][3] + bv.y);
        }
    }
}

// ============================================================================
// Attention A1 (state kernel): per (bh, chunk): M = V^T K * 0.125 -> g_Mh (fp16).
// Loads only K,V. One MMA phase. 128 threads (4 warps), warp tile 16x64.
// ============================================================================
__global__ void __launch_bounds__(128) attn_state_kernel()
{
    __shared__ __half sK[64 * 64], sV[64 * 64];

    const int tid = threadIdx.x, lane = tid & 31, w = tid >> 5;
    const int chunk = blockIdx.x, bh = blockIdx.y;
    const int b = bh >> 4, h = bh & 15;

    const uint32_t k_s = smem_u32(sK), v_s = smem_u32(sV);

    const __half* base = g_qkvh + (size_t)(b * Lx + chunk * CKx) * (3 * Dx) + h * DHx;
    #pragma unroll
    for (int j = 0; j < 4; j++) {
        int e = tid + j * 128;
        int r = e >> 3, c16 = e & 7;
        uint32_t off = (uint32_t)(r * 128 + ((c16 ^ (r & 7)) << 4));
        const __half* src = base + (size_t)r * (3 * Dx) + c16 * 8;
        CP16(k_s + off, src + Dx);
        CP16(v_s + off, src + 2 * Dx);
    }
    CP_COMMIT();
    CP_WAIT0();
    __syncthreads();

    const int lrow = lane & 15, lkc = lane >> 4;
    const int erow = lane >> 2, ecol = (lane & 3) * 2;

    float accM[8][4];
    #pragma unroll
    for (int nt = 0; nt < 8; nt++)
        #pragma unroll
        for (int i = 0; i < 4; i++) accM[nt][i] = 0.f;

    const int arow_lo = (lane & 7) + ((lane >> 4) << 3);
    const uint32_t ac16 = (uint32_t)(((w * 16) >> 3) + ((lane >> 3) & 1));

    #pragma unroll
    for (int ks = 0; ks < 4; ks++) {
        const int kbase = ks * 16;
        const int vr = kbase + arow_lo;
        uint32_t a[4];
        LDSM4T(a[0], a[1], a[2], a[3],
               v_s + (uint32_t)(vr * 128) + ((ac16 ^ (uint32_t)(vr & 7)) << 4));
        uint32_t bfr[8][2];
        #pragma unroll
        for (int nb = 0; nb < 4; nb++) {
            const int kr = kbase + lrow;
            const uint32_t c16 = (uint32_t)(nb * 2 + lkc);
            uint32_t r0, r1, r2, r3;
            LDSM4T(r0, r1, r2, r3, k_s + (uint32_t)(kr * 128) + ((c16 ^ (uint32_t)(kr & 7)) << 4));
            bfr[2 * nb][0] = r0; bfr[2 * nb][1] = r1;
            bfr[2 * nb + 1][0] = r2; bfr[2 * nb + 1][1] = r3;
        }
        #pragma unroll
        for (int nt = 0; nt < 8; nt++) MMA_F16(accM[nt], a, bfr[nt]);
    }

    __half* Mb = g_Mh + (size_t)(bh * NCH + chunk) * (DHx * DHx);
    #pragma unroll
    for (int nt = 0; nt < 8; nt++) {
        const int a0 = w * 16 + erow, j0 = nt * 8 + ecol;
        st2(Mb + a0 * 64 + j0, accM[nt][0] * 0.125f, accM[nt][1] * 0.125f);
        st2(Mb + (a0 + 8) * 64 + j0, accM[nt][2] * 0.125f, accM[nt][3] * 0.125f);
    }
}

// ---------------------------------------------------------------------------
// Exclusive prefix over chunks, 2 threads per element strand; fp16 M in,
// fp32 accumulate, fp16 P out.
// ---------------------------------------------------------------------------
__global__ void __launch_bounds__(256) prefix_kernel()
{
    __shared__ float tot[128];

    const int tid = threadIdx.x;
    const int el = tid & 127;
    const int half = tid >> 7;
    const int bh = blockIdx.y;
    const int e = blockIdx.x * 128 + el;
    size_t base = (size_t)bh * NCH * (DHx * DHx) + e
                + (size_t)(half * 16) * (DHx * DHx);

    float m[16];
    #pragma unroll
    for (int c = 0; c < 16; c++)
        m[c] = __half2float(g_Mh[base + (size_t)c * (DHx * DHx)]);

    float pre[16];
    float acc = 0.f;
    #pragma unroll
    for (int c = 0; c < 16; c++) { pre[c] = acc; acc += m[c]; }

    if (half == 0) tot[el] = acc;
    __syncthreads();
    const float add = half ? tot[el] : 0.f;

    #pragma unroll
    for (int c = 0; c < 16; c++)
        g_Ph[base + (size_t)c * (DHx * DHx)] = __float2half_rn(add + pre[c]);
}

// ============================================================================
// Attention A2 (fused output kernel): per (bh, chunk):
//   phase 1: accS = Q K^T  AND  accY = Q P^T  (shared Q fragments)
//   phase 2: accY += mask(accS)*0.125 @ V, with S converted IN REGISTERS
//            (accumulator fragment == A-operand fragment layout; no smem/sync)
//   y -> g_yh fp16 (single store).  128 threads (4 warps), warp tile 16x64.
// ============================================================================
__global__ void __launch_bounds__(128) attn_fused_kernel()
{
    __shared__ __half sQ[64 * 64], sK[64 * 64], sV[64 * 64], sP[64 * 64];

    const int tid = threadIdx.x, lane = tid & 31, w = tid >> 5;
    const int chunk = blockIdx.x, bh = blockIdx.y;
    const int b = bh >> 4, h = bh & 15;

    const uint32_t q_s = smem_u32(sQ), k_s = smem_u32(sK);
    const uint32_t v_s = smem_u32(sV), p_s = smem_u32(sP);

    const __half* base = g_qkvh + (size_t)(b * Lx + chunk * CKx) * (3 * Dx) + h * DHx;
    const __half* Pbase = g_Ph + (size_t)(bh * NCH + chunk) * (DHx * DHx);
    #pragma unroll
    for (int j = 0; j < 4; j++) {
        int e = tid + j * 128;
        int r = e >> 3, c16 = e & 7;
        uint32_t off = (uint32_t)(r * 128 + ((c16 ^ (r & 7)) << 4));
        const __half* src = base + (size_t)r * (3 * Dx) + c16 * 8;
        CP16(q_s + off, src);
        CP16(k_s + off, src + Dx);
        CP16(v_s + off, src + 2 * Dx);
        CP16(p_s + off, Pbase + r * 64 + c16 * 8);
    }
    CP_COMMIT();
    CP_WAIT0();
    __syncthreads();

    const int lrow = lane & 15, lkc = lane >> 4, l7 = lrow & 7;
    const int erow = lane >> 2, ecol = (lane & 3) * 2;
    const uint32_t aRowOff = (uint32_t)((w * 16 + lrow) * 128);

    // ---- Phase 1: accS = Q K^T ; accY = Q P^T (Q frags shared per ks) ----
    float accS[8][4], accY[8][4];
    #pragma unroll
    for (int nt = 0; nt < 8; nt++)
        #pragma unroll
        for (int i = 0; i < 4; i++) { accS[nt][i] = 0.f; accY[nt][i] = 0.f; }

    #pragma unroll
    for (int ks = 0; ks < 4; ks++) {
        const uint32_t swz = (uint32_t)(((ks * 2 + lkc) ^ l7) << 4);
        uint32_t a[4];
        LDSM4(a[0], a[1], a[2], a[3], q_s + aRowOff + swz);

        uint32_t bk[8][2];
        #pragma unroll
        for (int p = 0; p < 4; p++) {
            uint32_t r0, r1, r2, r3;
            LDSM4(r0, r1, r2, r3, k_s + (uint32_t)((p * 16 + lrow) * 128) + swz);
            bk[2 * p][0] = r0; bk[2 * p + 1][0] = r1;
            bk[2 * p][1] = r2; bk[2 * p + 1][1] = r3;
        }
        #pragma unroll
        for (int nt = 0; nt < 8; nt++) MMA_F16(accS[nt], a, bk[nt]);

        uint32_t bp[8][2];
        #pragma unroll
        for (int p = 0; p < 4; p++) {
            uint32_t r0, r1, r2, r3;
            LDSM4(r0, r1, r2, r3, p_s + (uint32_t)((p * 16 + lrow) * 128) + swz);
            bp[2 * p][0] = r0; bp[2 * p + 1][0] = r1;
            bp[2 * p][1] = r2; bp[2 * p + 1][1] = r3;
        }
        #pragma unroll
        for (int nt = 0; nt < 8; nt++) MMA_F16(accY[nt], a, bp[nt]);
    }

    // ---- Phase 2: accY += mask(S) V ; S fragments built in registers ----
    // A-frag(k16 slab ks) regs: a0=(r,k0k1), a1=(r+8,k0k1), a2=(r,k8k9),
    // a3=(r+8,k8k9) with k pair = (lane&3)*2 — identical positions to the
    // C-fragments of accS tiles nt=2ks (k 0..7) and nt=2ks+1 (k 8..15).
    const int i0 = w * 16 + erow, i1 = i0 + 8;
    #pragma unroll
    for (int ks = 0; ks < 4; ks++) {
        const int kbase = ks * 16;
        uint32_t a[4];
        {
            const int nt0 = 2 * ks, nt1 = nt0 + 1;
            const int j0 = nt0 * 8 + ecol, j1 = nt1 * 8 + ecol;
            a[0] = pack_mask(accS[nt0][0], accS[nt0][1], i0, j0);
            a[1] = pack_mask(accS[nt0][2], accS[nt0][3], i1, j0);
            a[2] = pack_mask(accS[nt1][0], accS[nt1][1], i0, j1);
            a[3] = pack_mask(accS[nt1][2], accS[nt1][3], i1, j1);
        }
        uint32_t bfr[8][2];
        #pragma unroll
        for (int nb = 0; nb < 4; nb++) {
            const int vr = kbase + lrow;
            const uint32_t c16 = (uint32_t)(nb * 2 + lkc);
            uint32_t r0, r1, r2, r3;
            LDSM4T(r0, r1, r2, r3, v_s + (uint32_t)(vr * 128) + ((c16 ^ (uint32_t)(vr & 7)) << 4));
            bfr[2 * nb][0] = r0; bfr[2 * nb][1] = r1;
            bfr[2 * nb + 1][0] = r2; bfr[2 * nb + 1][1] = r3;
        }
        #pragma unroll
        for (int nt = 0; nt < 8; nt++) MMA_F16(accY[nt], a, bfr[nt]);
    }

    __half* yb = g_yh + (size_t)(b * Lx + chunk * CKx) * Dx + h * DHx;
    #pragma unroll
    for (int nt = 0; nt < 8; nt++) {
        const int j0 = nt * 8 + ecol;
        st2(yb + (size_t)i0 * Dx + j0, accY[nt][0], accY[nt][1]);
        st2(yb + (size_t)i1 * Dx + j0, accY[nt][2], accY[nt][3]);
    }
}

// ---------------------------------------------------------------------------
extern "C" void kernel_launch(void* const* d_in, const int* in_sizes, int n_in,
                              void* d_out, int out_size)
{
    const float* x      = (const float*)d_in[0];   // [2,2048,1024]
    const float* Wqkv_w = (const float*)d_in[1];   // [3072,1024]
    const float* Wqkv_b = (const float*)d_in[2];   // [3072]
    const float* out_w  = (const float*)d_in[3];   // [1024,1024]
    const float* out_b  = (const float*)d_in[4];   // [1024]
    float* out = (float*)d_out;                    // [2,2048,1024]

    __half *qkvh_ptr, *xh_ptr, *wq_ptr, *wo_ptr, *yh_ptr;
    cudaGetSymbolAddress((void**)&qkvh_ptr, g_qkvh);
    cudaGetSymbolAddress((void**)&xh_ptr, g_xh);
    cudaGetSymbolAddress((void**)&wq_ptr, g_wqh);
    cudaGetSymbolAddress((void**)&wo_ptr, g_woh);
    cudaGetSymbolAddress((void**)&yh_ptr, g_yh);

    cudaFuncSetAttribute(gemm_tc_bias<__half>,
                         cudaFuncAttributeMaxDynamicSharedMemorySize, TSMEM_TOTAL);
    cudaFuncSetAttribute(gemm_tc_bias<float>,
                         cudaFuncAttributeMaxDynamicSharedMemorySize, TSMEM_TOTAL);

    // 0. fused fp16 conversion of GEMM operands (one launch)
    f2h_all_kernel<<<(NX4 + NQ4 + NO4 + 255) / 256, 256>>>(x, Wqkv_w, out_w);

    // 1. QKV projection -> fp16 qkv
    gemm_tc_bias<__half><<<dim3(3072 / TBN, ROWSx / TBM), 256, TSMEM_TOTAL>>>(
        xh_ptr, wq_ptr, Wqkv_b, qkvh_ptr, ROWSx, 3 * Dx, Dx);

    // 2a. Per-chunk states M = V^T K -> fp16
    attn_state_kernel<<<dim3(NCH, BHx), 128>>>();

    // 2b. Exclusive prefix of states -> fp16 P
    prefix_kernel<<<dim3(32, BHx), 256>>>();

    // 2c. Fused output: y = mask(QK^T)*scale @ V + Q P^T -> g_yh
    attn_fused_kernel<<<dim3(NCH, BHx), 128>>>();

    // 3. Output projection -> fp32 out
    gemm_tc_bias<float><<<dim3(Dx / TBN, ROWSx / TBM), 256, TSMEM_TOTAL>>>(
        yh_ptr, wo_ptr, out_b, out, ROWSx, Dx, Dx);
}